// round 12
// baseline (speedup 1.0000x reference)
#include <cuda_runtime.h>
#include <cuda_fp16.h>

#define NTHREADS 256
#define MAX_BLOCKS 8192

#define C_PER_SAMPLE 7.1624450756f  // prior+lik constants per sample
#define C_ENTROPY    5.6757541328f  // 0.5*4*(1+log 2pi)

__device__ __forceinline__ __half2 u2h(unsigned int u)
{
    __half2 r;
    *reinterpret_cast<unsigned int*>(&r) = u;
    return r;
}

// ---------------- weights: l1 fp32, l2/l3 duplicated fp16 pairs -------------
// Each uint lane = __half2 {w, w} (same weight both lanes; lanes carry rowA/rowB).
struct WAll {
    float4 l1 [3][20];     // (W1[0][j], W1[1][j], b1[j], 0)  fp32
    uint4  l2h[3][20][3];  // [j][t]: lanes k=4t..4t+3 of W2[j][k] (k>=10 -> 0)
    uint4  l3h[3][6][3];   // [o][t]: lanes k=4t..4t+3 of W3[k][o] (pads 0)
    uint4  b2h[3][3];      // lanes k of b2[k] (k>=10 -> 0)
    uint4  b3h[3][2];      // lanes o of b3[o] (o>=OUT -> 0)
};

__constant__ WAll c_w;
__device__   WAll g_stage;
__device__ double g_partial[MAX_BLOCKS];
__device__ unsigned int g_ticket;   // zero-init; last block resets (graph-replay safe)

__device__ __forceinline__ unsigned int dup16(float w)
{
    unsigned short s = __half_as_ushort(__float2half_rn(w));
    return (unsigned int)s * 0x10001u;
}

// ---------------------------------------------------------------------------
__global__ void pack_kernel(
    const float* mW1, const float* mb1, const float* mW2, const float* mb2,
    const float* mW3, const float* mb3,
    const float* dW1, const float* db1, const float* dW2, const float* db2,
    const float* dW3, const float* db3,
    const float* oW1, const float* ob1, const float* oW2, const float* ob2,
    const float* oW3, const float* ob3)
{
    const float* W1[3] = {mW1, dW1, oW1};
    const float* B1[3] = {mb1, db1, ob1};
    const float* W2[3] = {mW2, dW2, oW2};
    const float* B2[3] = {mb2, db2, ob2};
    const float* W3[3] = {mW3, dW3, oW3};
    const float* B3[3] = {mb3, db3, ob3};
    const int OUT[3] = {4, 4, 6};
    int t = threadIdx.x;

    for (int i = t; i < 60; i += blockDim.x) {          // layer1 fp32
        int m = i / 20, j = i % 20;
        g_stage.l1[m][j] = make_float4(W1[m][j], W1[m][20 + j], B1[m][j], 0.0f);
    }
    for (int i = t; i < 180; i += blockDim.x) {         // layer2 fp16 dup
        int m = i / 60, r = i % 60, j = r / 3, tt = r % 3;
        unsigned int v[4];
#pragma unroll
        for (int s = 0; s < 4; s++) {
            int k = 4 * tt + s;
            v[s] = (k < 10) ? dup16(W2[m][j * 10 + k]) : 0u;
        }
        g_stage.l2h[m][j][tt] = make_uint4(v[0], v[1], v[2], v[3]);
    }
    for (int i = t; i < 54; i += blockDim.x) {          // layer3 fp16 dup
        int m = i / 18, r = i % 18, o = r / 3, tt = r % 3;
        int Om = OUT[m];
        unsigned int v[4];
#pragma unroll
        for (int s = 0; s < 4; s++) {
            int k = 4 * tt + s;
            v[s] = (k < 10 && o < Om) ? dup16(W3[m][k * Om + o]) : 0u;
        }
        g_stage.l3h[m][o][tt] = make_uint4(v[0], v[1], v[2], v[3]);
    }
    for (int i = t; i < 9; i += blockDim.x) {           // b2 fp16 dup
        int m = i / 3, tt = i % 3;
        unsigned int v[4];
#pragma unroll
        for (int s = 0; s < 4; s++) {
            int k = 4 * tt + s;
            v[s] = (k < 10) ? dup16(B2[m][k]) : 0u;
        }
        g_stage.b2h[m][tt] = make_uint4(v[0], v[1], v[2], v[3]);
    }
    for (int i = t; i < 6; i += blockDim.x) {           // b3 fp16 dup
        int m = i / 2, tt = i % 2;
        int Om = OUT[m];
        unsigned int v[4];
#pragma unroll
        for (int s = 0; s < 4; s++) {
            int o = 4 * tt + s;
            v[s] = (o < Om) ? dup16(B3[m][o]) : 0u;
        }
        g_stage.b3h[m][tt] = make_uint4(v[0], v[1], v[2], v[3]);
    }
}

// ---------------------------------------------------------------------------
// Two rows per thread. Layer 1 fp32 (exact y path); layers 2+3 HFMA2 with
// lanes = {rowA, rowB}. j-streaming: no h array.
template <int M, int OUT>
__device__ __forceinline__ void mlp2r(float y0A, float y1A, float y0B, float y1B,
                                      float* outA, float* outB)
{
    __half2 acc[10];
    {
        uint4 b0 = c_w.b2h[M][0];
        uint4 b1 = c_w.b2h[M][1];
        uint4 b2q = c_w.b2h[M][2];
        acc[0] = u2h(b0.x); acc[1] = u2h(b0.y); acc[2] = u2h(b0.z); acc[3] = u2h(b0.w);
        acc[4] = u2h(b1.x); acc[5] = u2h(b1.y); acc[6] = u2h(b1.z); acc[7] = u2h(b1.w);
        acc[8] = u2h(b2q.x); acc[9] = u2h(b2q.y);
    }
#pragma unroll
    for (int j = 0; j < 20; j++) {
        float4 v = c_w.l1[M][j];
        float hA = fmaxf(fmaf(v.x, y0A, fmaf(v.y, y1A, v.z)), 0.0f);
        float hB = fmaxf(fmaf(v.x, y0B, fmaf(v.y, y1B, v.z)), 0.0f);
        __half2 hp = __floats2half2_rn(hA, hB);
        uint4 w0 = c_w.l2h[M][j][0];
        uint4 w1 = c_w.l2h[M][j][1];
        uint4 w2 = c_w.l2h[M][j][2];
        acc[0] = __hfma2(u2h(w0.x), hp, acc[0]);
        acc[1] = __hfma2(u2h(w0.y), hp, acc[1]);
        acc[2] = __hfma2(u2h(w0.z), hp, acc[2]);
        acc[3] = __hfma2(u2h(w0.w), hp, acc[3]);
        acc[4] = __hfma2(u2h(w1.x), hp, acc[4]);
        acc[5] = __hfma2(u2h(w1.y), hp, acc[5]);
        acc[6] = __hfma2(u2h(w1.z), hp, acc[6]);
        acc[7] = __hfma2(u2h(w1.w), hp, acc[7]);
        acc[8] = __hfma2(u2h(w2.x), hp, acc[8]);
        acc[9] = __hfma2(u2h(w2.y), hp, acc[9]);
    }
    const __half2 z2 = __float2half2_rn(0.0f);
#pragma unroll
    for (int k = 0; k < 10; k++) acc[k] = __hmax2(acc[k], z2);

#pragma unroll
    for (int o = 0; o < OUT; o++) {
        uint4 bq = c_w.b3h[M][o >> 2];
        unsigned int bu = (o & 3) == 0 ? bq.x : (o & 3) == 1 ? bq.y
                        : (o & 3) == 2 ? bq.z : bq.w;
        __half2 s = u2h(bu);
        uint4 w0 = c_w.l3h[M][o][0];
        uint4 w1 = c_w.l3h[M][o][1];
        uint4 w2 = c_w.l3h[M][o][2];
        s = __hfma2(u2h(w0.x), acc[0], s);
        s = __hfma2(u2h(w0.y), acc[1], s);
        s = __hfma2(u2h(w0.z), acc[2], s);
        s = __hfma2(u2h(w0.w), acc[3], s);
        s = __hfma2(u2h(w1.x), acc[4], s);
        s = __hfma2(u2h(w1.y), acc[5], s);
        s = __hfma2(u2h(w1.z), acc[6], s);
        s = __hfma2(u2h(w1.w), acc[7], s);
        s = __hfma2(u2h(w2.x), acc[8], s);
        s = __hfma2(u2h(w2.y), acc[9], s);
        float2 sf = __half22float2(s);
        outA[o] = sf.x;
        outB[o] = sf.y;
    }
}

__device__ __forceinline__ float softplus_f(float x)
{
    return fmaxf(x, 0.0f) + __logf(1.0f + __expf(-fabsf(x)));
}

// Scalar fp32 per-row sample term (known-good from R9).
__device__ __forceinline__ float sample_term(
    const float4 z, const float* mu, const float* off,
    float d0, float d1, float d2, float d3, float yx100, float yy100)
{
    float xi0 = fmaf(d0, z.x, mu[0]);
    float xi1 = fmaf(d1, z.y, fmaf(off[0], z.x, mu[1]));
    float xi2 = fmaf(d2, z.z, fmaf(off[2], z.y, fmaf(off[1], z.x, mu[2])));
    float xi3 = fmaf(d3, z.w, fmaf(off[5], z.z,
                  fmaf(off[4], z.y, fmaf(off[3], z.x, mu[3]))));

    float a2 = xi1 + xi2;
    float a3 = a2 + xi3;
    float s1, c1, s2, c2, s3, c3;
    __sincosf(xi1, &s1, &c1);
    __sincosf(a2,  &s2, &c2);
    __sincosf(a3,  &s3, &c3);

    float px = fmaf(0.5f, c1, fmaf(0.5f, c2, c3));
    float py = xi0 + fmaf(0.5f, s1, fmaf(0.5f, s2, s3));

    float rx = fmaf(-100.0f, px, yx100);
    float ry = fmaf(-100.0f, py, yy100);

    float s123 = fmaf(xi1, xi1, fmaf(xi2, xi2, xi3 * xi3));
    float tq = fmaf(xi0 * -8.0f, xi0, -2.0f * s123);
    float r2 = fmaf(rx, rx, ry * ry);
    return fmaf(-0.5f, r2, tq);
}

// ---------------------------------------------------------------------------
// 5 blocks/SM -> 51-reg budget, 10 warps/SMSP: enough eligible warps to cover
// LDC/F2FP/MUFU latency that stalled the occ-43% HFMA2 variant.
__global__ void __launch_bounds__(NTHREADS, 5)
vi_kernel(const float* __restrict__ y, const float* __restrict__ zs, int N,
          float* __restrict__ out)
{
    __shared__ double sred[NTHREADS];
    __shared__ float wsum[NTHREADS / 32];
    __shared__ int sh_last;

    int tid = threadIdx.x;
    int g = blockIdx.x * NTHREADS + tid;
    int n0 = 2 * g, n1 = n0 + 1;
    float val = 0.0f;

    if (n0 < N) {
        bool two = (n1 < N);
        float4 yv;
        if (two) {
            yv = ((const float4*)y)[g];
        } else {
            float2 ya = ((const float2*)y)[n0];
            yv = make_float4(ya.x, ya.y, ya.x, ya.y);
            n1 = n0;
        }

        const float4* zpA = (const float4*)zs + (size_t)n0 * 8;
        const float4* zpB = (const float4*)zs + (size_t)n1 * 8;

        float muA[4], muB[4], ldA[4], ldB[4], ofA[6], ofB[6];
        mlp2r<0, 4>(yv.x, yv.y, yv.z, yv.w, muA, muB);
        mlp2r<1, 4>(yv.x, yv.y, yv.z, yv.w, ldA, ldB);
        mlp2r<2, 6>(yv.x, yv.y, yv.z, yv.w, ofA, ofB);

        float d0A = softplus_f(ldA[0]), d0B = softplus_f(ldB[0]);
        float d1A = softplus_f(ldA[1]), d1B = softplus_f(ldB[1]);
        float d2A = softplus_f(ldA[2]), d2B = softplus_f(ldB[2]);
        float d3A = softplus_f(ldA[3]), d3B = softplus_f(ldB[3]);

        float yxA = yv.x * 100.0f, yyA = yv.y * 100.0f;
        float yxB = yv.z * 100.0f, yyB = yv.w * 100.0f;

        float accA = 0.0f, accB = 0.0f;
#pragma unroll
        for (int p = 0; p < 8; p++) {
            float4 za = __ldg(&zpA[p]);     // both loads issued back-to-back
            float4 zb = __ldg(&zpB[p]);     // (MLP=2); covered by 10 warps/SMSP
            accA += sample_term(za, muA, ofA, d0A, d1A, d2A, d3A, yxA, yyA);
            accB += sample_term(zb, muB, ofB, d0B, d1B, d2B, d3B, yxB, yyB);
        }

        float vA = fmaf(accA, 0.125f, C_PER_SAMPLE) + C_ENTROPY +
                   __logf(d0A * d1A * d2A * d3A);
        float vB = fmaf(accB, 0.125f, C_PER_SAMPLE) + C_ENTROPY +
                   __logf(d0B * d1B * d2B * d3B);
        val = two ? (vA + vB) : vA;
    }

    // ---- deterministic block reduction ----
#pragma unroll
    for (int o = 16; o > 0; o >>= 1)
        val += __shfl_down_sync(0xffffffffu, val, o);
    if ((tid & 31) == 0) wsum[tid >> 5] = val;
    __syncthreads();
    if (tid == 0) {
        double s = 0.0;
#pragma unroll
        for (int w = 0; w < NTHREADS / 32; w++) s += (double)wsum[w];
        g_partial[blockIdx.x] = s;
        __threadfence();
        unsigned t = atomicAdd(&g_ticket, 1u);
        sh_last = (t == gridDim.x - 1) ? 1 : 0;
    }
    __syncthreads();

    // ---- fused finalize: last block reduces partials deterministically ----
    if (sh_last) {
        __threadfence();
        double s = 0.0;
        for (int i = tid; i < (int)gridDim.x; i += NTHREADS)
            s += __ldcg(&g_partial[i]);
        sred[tid] = s;
        __syncthreads();
#pragma unroll
        for (int st = NTHREADS / 2; st > 0; st >>= 1) {
            if (tid < st) sred[tid] += sred[tid + st];
            __syncthreads();
        }
        if (tid == 0) {
            out[0] = (float)(sred[0] / (double)N);
            __threadfence();
            g_ticket = 0;   // reset for next graph replay
        }
    }
}

// ---------------------------------------------------------------------------
extern "C" void kernel_launch(void* const* d_in, const int* in_sizes, int n_in,
                              void* d_out, int out_size)
{
    const float* y  = (const float*)d_in[0];
    const float* zs = (const float*)d_in[1];
    int N = in_sizes[0] / 2;
    int npairs = (N + 1) / 2;
    int nblocks = (npairs + NTHREADS - 1) / NTHREADS;
    if (nblocks > MAX_BLOCKS) nblocks = MAX_BLOCKS;

    pack_kernel<<<1, 128>>>(
        (const float*)d_in[2],  (const float*)d_in[3],  (const float*)d_in[4],
        (const float*)d_in[5],  (const float*)d_in[6],  (const float*)d_in[7],
        (const float*)d_in[8],  (const float*)d_in[9],  (const float*)d_in[10],
        (const float*)d_in[11], (const float*)d_in[12], (const float*)d_in[13],
        (const float*)d_in[14], (const float*)d_in[15], (const float*)d_in[16],
        (const float*)d_in[17], (const float*)d_in[18], (const float*)d_in[19]);

    void* caddr = nullptr;
    void* saddr = nullptr;
    cudaGetSymbolAddress(&caddr, c_w);
    cudaGetSymbolAddress(&saddr, g_stage);
    cudaMemcpyAsync(caddr, saddr, sizeof(WAll), cudaMemcpyDeviceToDevice, 0);

    vi_kernel<<<nblocks, NTHREADS>>>(y, zs, N, (float*)d_out);
}

// round 13
// speedup vs baseline: 1.0901x; 1.0901x over previous
#include <cuda_runtime.h>
#include <cuda_fp16.h>

#define NTHREADS 256
#define MAX_BLOCKS 8192

#define C_PER_SAMPLE 7.1624450756f  // prior+lik constants per sample
#define C_ENTROPY    5.6757541328f  // 0.5*4*(1+log 2pi)

__device__ __forceinline__ __half2 u2h(unsigned int u)
{
    __half2 r;
    *reinterpret_cast<unsigned int*>(&r) = u;
    return r;
}

// ---------------- weights: l1 fp32, l2/l3 duplicated fp16 pairs -------------
// Each uint lane = __half2 {w, w}. Lives in smem at runtime (LDS floor 2-4
// beats the LDC->LDC floor 8 that stalled the constant-memory variant).
struct WAll {
    float4 l1 [3][20];     // (W1[0][j], W1[1][j], b1[j], 0)  fp32
    uint4  l2h[3][20][3];  // [j][t]: lanes k=4t..4t+3 of W2[j][k] (k>=10 -> 0)
    uint4  l3h[3][6][3];   // [o][t]: lanes k=4t..4t+3 of W3[k][o] (pads 0)
    uint4  b2h[3][3];      // lanes k of b2[k] (k>=10 -> 0)
    uint4  b3h[3][2];      // lanes o of b3[o] (o>=OUT -> 0)
};
#define WALL_U4 (sizeof(WAll) / 16)

__device__ WAll g_stage;
__device__ double g_partial[MAX_BLOCKS];
__device__ unsigned int g_ticket;   // zero-init; last block resets (graph-replay safe)

__device__ __forceinline__ unsigned int dup16(float w)
{
    unsigned short s = __half_as_ushort(__float2half_rn(w));
    return (unsigned int)s * 0x10001u;
}

// ---------------------------------------------------------------------------
__global__ void pack_kernel(
    const float* mW1, const float* mb1, const float* mW2, const float* mb2,
    const float* mW3, const float* mb3,
    const float* dW1, const float* db1, const float* dW2, const float* db2,
    const float* dW3, const float* db3,
    const float* oW1, const float* ob1, const float* oW2, const float* ob2,
    const float* oW3, const float* ob3)
{
    const float* W1[3] = {mW1, dW1, oW1};
    const float* B1[3] = {mb1, db1, ob1};
    const float* W2[3] = {mW2, dW2, oW2};
    const float* B2[3] = {mb2, db2, ob2};
    const float* W3[3] = {mW3, dW3, oW3};
    const float* B3[3] = {mb3, db3, ob3};
    const int OUT[3] = {4, 4, 6};
    int t = threadIdx.x;

    for (int i = t; i < 60; i += blockDim.x) {          // layer1 fp32
        int m = i / 20, j = i % 20;
        g_stage.l1[m][j] = make_float4(W1[m][j], W1[m][20 + j], B1[m][j], 0.0f);
    }
    for (int i = t; i < 180; i += blockDim.x) {         // layer2 fp16 dup
        int m = i / 60, r = i % 60, j = r / 3, tt = r % 3;
        unsigned int v[4];
#pragma unroll
        for (int s = 0; s < 4; s++) {
            int k = 4 * tt + s;
            v[s] = (k < 10) ? dup16(W2[m][j * 10 + k]) : 0u;
        }
        g_stage.l2h[m][j][tt] = make_uint4(v[0], v[1], v[2], v[3]);
    }
    for (int i = t; i < 54; i += blockDim.x) {          // layer3 fp16 dup
        int m = i / 18, r = i % 18, o = r / 3, tt = r % 3;
        int Om = OUT[m];
        unsigned int v[4];
#pragma unroll
        for (int s = 0; s < 4; s++) {
            int k = 4 * tt + s;
            v[s] = (k < 10 && o < Om) ? dup16(W3[m][k * Om + o]) : 0u;
        }
        g_stage.l3h[m][o][tt] = make_uint4(v[0], v[1], v[2], v[3]);
    }
    for (int i = t; i < 9; i += blockDim.x) {           // b2 fp16 dup
        int m = i / 3, tt = i % 3;
        unsigned int v[4];
#pragma unroll
        for (int s = 0; s < 4; s++) {
            int k = 4 * tt + s;
            v[s] = (k < 10) ? dup16(B2[m][k]) : 0u;
        }
        g_stage.b2h[m][tt] = make_uint4(v[0], v[1], v[2], v[3]);
    }
    for (int i = t; i < 6; i += blockDim.x) {           // b3 fp16 dup
        int m = i / 2, tt = i % 2;
        int Om = OUT[m];
        unsigned int v[4];
#pragma unroll
        for (int s = 0; s < 4; s++) {
            int o = 4 * tt + s;
            v[s] = (o < Om) ? dup16(B3[m][o]) : 0u;
        }
        g_stage.b3h[m][tt] = make_uint4(v[0], v[1], v[2], v[3]);
    }
}

// ---------------------------------------------------------------------------
// Two rows per thread. Layer 1 fp32 (exact y path); layers 2+3 HFMA2 with
// lanes = {rowA, rowB}. j-streaming; weights from smem (broadcast LDS).
template <int M, int OUT>
__device__ __forceinline__ void mlp2r(const WAll* __restrict__ w,
                                      float y0A, float y1A, float y0B, float y1B,
                                      float* outA, float* outB)
{
    __half2 acc[10];
    {
        uint4 b0 = w->b2h[M][0];
        uint4 b1 = w->b2h[M][1];
        uint4 b2q = w->b2h[M][2];
        acc[0] = u2h(b0.x); acc[1] = u2h(b0.y); acc[2] = u2h(b0.z); acc[3] = u2h(b0.w);
        acc[4] = u2h(b1.x); acc[5] = u2h(b1.y); acc[6] = u2h(b1.z); acc[7] = u2h(b1.w);
        acc[8] = u2h(b2q.x); acc[9] = u2h(b2q.y);
    }
#pragma unroll
    for (int j = 0; j < 20; j++) {
        float4 v = w->l1[M][j];
        float hA = fmaxf(fmaf(v.x, y0A, fmaf(v.y, y1A, v.z)), 0.0f);
        float hB = fmaxf(fmaf(v.x, y0B, fmaf(v.y, y1B, v.z)), 0.0f);
        __half2 hp = __floats2half2_rn(hA, hB);
        uint4 w0 = w->l2h[M][j][0];
        uint4 w1 = w->l2h[M][j][1];
        uint4 w2 = w->l2h[M][j][2];
        acc[0] = __hfma2(u2h(w0.x), hp, acc[0]);
        acc[1] = __hfma2(u2h(w0.y), hp, acc[1]);
        acc[2] = __hfma2(u2h(w0.z), hp, acc[2]);
        acc[3] = __hfma2(u2h(w0.w), hp, acc[3]);
        acc[4] = __hfma2(u2h(w1.x), hp, acc[4]);
        acc[5] = __hfma2(u2h(w1.y), hp, acc[5]);
        acc[6] = __hfma2(u2h(w1.z), hp, acc[6]);
        acc[7] = __hfma2(u2h(w1.w), hp, acc[7]);
        acc[8] = __hfma2(u2h(w2.x), hp, acc[8]);
        acc[9] = __hfma2(u2h(w2.y), hp, acc[9]);
    }
    const __half2 z2 = __float2half2_rn(0.0f);
#pragma unroll
    for (int k = 0; k < 10; k++) acc[k] = __hmax2(acc[k], z2);

#pragma unroll
    for (int o = 0; o < OUT; o++) {
        uint4 bq = w->b3h[M][o >> 2];
        unsigned int bu = (o & 3) == 0 ? bq.x : (o & 3) == 1 ? bq.y
                        : (o & 3) == 2 ? bq.z : bq.w;
        __half2 s = u2h(bu);
        uint4 w0 = w->l3h[M][o][0];
        uint4 w1 = w->l3h[M][o][1];
        uint4 w2 = w->l3h[M][o][2];
        s = __hfma2(u2h(w0.x), acc[0], s);
        s = __hfma2(u2h(w0.y), acc[1], s);
        s = __hfma2(u2h(w0.z), acc[2], s);
        s = __hfma2(u2h(w0.w), acc[3], s);
        s = __hfma2(u2h(w1.x), acc[4], s);
        s = __hfma2(u2h(w1.y), acc[5], s);
        s = __hfma2(u2h(w1.z), acc[6], s);
        s = __hfma2(u2h(w1.w), acc[7], s);
        s = __hfma2(u2h(w2.x), acc[8], s);
        s = __hfma2(u2h(w2.y), acc[9], s);
        float2 sf = __half22float2(s);
        outA[o] = sf.x;
        outB[o] = sf.y;
    }
}

__device__ __forceinline__ float softplus_f(float x)
{
    return fmaxf(x, 0.0f) + __logf(1.0f + __expf(-fabsf(x)));
}

// Scalar fp32 per-row sample term (known-good from R9).
__device__ __forceinline__ float sample_term(
    const float4 z, const float* mu, const float* off,
    float d0, float d1, float d2, float d3, float yx100, float yy100)
{
    float xi0 = fmaf(d0, z.x, mu[0]);
    float xi1 = fmaf(d1, z.y, fmaf(off[0], z.x, mu[1]));
    float xi2 = fmaf(d2, z.z, fmaf(off[2], z.y, fmaf(off[1], z.x, mu[2])));
    float xi3 = fmaf(d3, z.w, fmaf(off[5], z.z,
                  fmaf(off[4], z.y, fmaf(off[3], z.x, mu[3]))));

    float a2 = xi1 + xi2;
    float a3 = a2 + xi3;
    float s1, c1, s2, c2, s3, c3;
    __sincosf(xi1, &s1, &c1);
    __sincosf(a2,  &s2, &c2);
    __sincosf(a3,  &s3, &c3);

    float px = fmaf(0.5f, c1, fmaf(0.5f, c2, c3));
    float py = xi0 + fmaf(0.5f, s1, fmaf(0.5f, s2, s3));

    float rx = fmaf(-100.0f, px, yx100);
    float ry = fmaf(-100.0f, py, yy100);

    float s123 = fmaf(xi1, xi1, fmaf(xi2, xi2, xi3 * xi3));
    float tq = fmaf(xi0 * -8.0f, xi0, -2.0f * s123);
    float r2 = fmaf(rx, rx, ry * ry);
    return fmaf(-0.5f, r2, tq);
}

// ---------------------------------------------------------------------------
__global__ void __launch_bounds__(NTHREADS, 5)
vi_kernel(const float* __restrict__ y, const float* __restrict__ zs, int N,
          float* __restrict__ out)
{
    __shared__ WAll s_w;
    __shared__ double sred[NTHREADS];
    __shared__ float wsum[NTHREADS / 32];
    __shared__ int sh_last;

    int tid = threadIdx.x;
    {
        const uint4* src = (const uint4*)&g_stage;
        uint4* dst = (uint4*)&s_w;
        for (int i = tid; i < (int)WALL_U4; i += NTHREADS)
            dst[i] = __ldg(&src[i]);
    }
    __syncthreads();

    int g = blockIdx.x * NTHREADS + tid;
    int n0 = 2 * g, n1 = n0 + 1;
    float val = 0.0f;

    if (n0 < N) {
        bool two = (n1 < N);
        float4 yv;
        if (two) {
            yv = ((const float4*)y)[g];
        } else {
            float2 ya = ((const float2*)y)[n0];
            yv = make_float4(ya.x, ya.y, ya.x, ya.y);
            n1 = n0;
        }

        const float4* zpA = (const float4*)zs + (size_t)n0 * 8;
        const float4* zpB = (const float4*)zs + (size_t)n1 * 8;

        float muA[4], muB[4], ldA[4], ldB[4], ofA[6], ofB[6];
        mlp2r<0, 4>(&s_w, yv.x, yv.y, yv.z, yv.w, muA, muB);
        mlp2r<1, 4>(&s_w, yv.x, yv.y, yv.z, yv.w, ldA, ldB);
        mlp2r<2, 6>(&s_w, yv.x, yv.y, yv.z, yv.w, ofA, ofB);

        float d0A = softplus_f(ldA[0]), d0B = softplus_f(ldB[0]);
        float d1A = softplus_f(ldA[1]), d1B = softplus_f(ldB[1]);
        float d2A = softplus_f(ldA[2]), d2B = softplus_f(ldB[2]);
        float d3A = softplus_f(ldA[3]), d3B = softplus_f(ldB[3]);

        float yxA = yv.x * 100.0f, yyA = yv.y * 100.0f;
        float yxB = yv.z * 100.0f, yyB = yv.w * 100.0f;

        float accA = 0.0f, accB = 0.0f;
#pragma unroll
        for (int p = 0; p < 8; p++) {
            float4 za = __ldg(&zpA[p]);
            float4 zb = __ldg(&zpB[p]);
            accA += sample_term(za, muA, ofA, d0A, d1A, d2A, d3A, yxA, yyA);
            accB += sample_term(zb, muB, ofB, d0B, d1B, d2B, d3B, yxB, yyB);
        }

        float vA = fmaf(accA, 0.125f, C_PER_SAMPLE) + C_ENTROPY +
                   __logf(d0A * d1A * d2A * d3A);
        float vB = fmaf(accB, 0.125f, C_PER_SAMPLE) + C_ENTROPY +
                   __logf(d0B * d1B * d2B * d3B);
        val = two ? (vA + vB) : vA;
    }

    // ---- deterministic block reduction ----
#pragma unroll
    for (int o = 16; o > 0; o >>= 1)
        val += __shfl_down_sync(0xffffffffu, val, o);
    if ((tid & 31) == 0) wsum[tid >> 5] = val;
    __syncthreads();
    if (tid == 0) {
        double s = 0.0;
#pragma unroll
        for (int w = 0; w < NTHREADS / 32; w++) s += (double)wsum[w];
        g_partial[blockIdx.x] = s;
        __threadfence();
        unsigned t = atomicAdd(&g_ticket, 1u);
        sh_last = (t == gridDim.x - 1) ? 1 : 0;
    }
    __syncthreads();

    // ---- fused finalize: last block reduces partials deterministically ----
    if (sh_last) {
        __threadfence();
        double s = 0.0;
        for (int i = tid; i < (int)gridDim.x; i += NTHREADS)
            s += __ldcg(&g_partial[i]);
        sred[tid] = s;
        __syncthreads();
#pragma unroll
        for (int st = NTHREADS / 2; st > 0; st >>= 1) {
            if (tid < st) sred[tid] += sred[tid + st];
            __syncthreads();
        }
        if (tid == 0) {
            out[0] = (float)(sred[0] / (double)N);
            __threadfence();
            g_ticket = 0;   // reset for next graph replay
        }
    }
}

// ---------------------------------------------------------------------------
extern "C" void kernel_launch(void* const* d_in, const int* in_sizes, int n_in,
                              void* d_out, int out_size)
{
    const float* y  = (const float*)d_in[0];
    const float* zs = (const float*)d_in[1];
    int N = in_sizes[0] / 2;
    int npairs = (N + 1) / 2;
    int nblocks = (npairs + NTHREADS - 1) / NTHREADS;
    if (nblocks > MAX_BLOCKS) nblocks = MAX_BLOCKS;

    pack_kernel<<<1, 128>>>(
        (const float*)d_in[2],  (const float*)d_in[3],  (const float*)d_in[4],
        (const float*)d_in[5],  (const float*)d_in[6],  (const float*)d_in[7],
        (const float*)d_in[8],  (const float*)d_in[9],  (const float*)d_in[10],
        (const float*)d_in[11], (const float*)d_in[12], (const float*)d_in[13],
        (const float*)d_in[14], (const float*)d_in[15], (const float*)d_in[16],
        (const float*)d_in[17], (const float*)d_in[18], (const float*)d_in[19]);

    vi_kernel<<<nblocks, NTHREADS>>>(y, zs, N, (float*)d_out);
}